// round 2
// baseline (speedup 1.0000x reference)
#include <cuda_runtime.h>

#define S_    512
#define P_    196
#define Q_    48
#define CB_   8
#define R_    32
#define C_    10
#define NMID  6

#define THREADS 256

// shared memory layout (in floats)
//  sx     [0      .. 9408)   x sample [p][q]
//  sM     [9408   .. 21952)  M [p][ab]  (also reused for y1/z as [p][b])
//  sG     [21952  .. 26048)  G tile [ab(64)][col(64)]  col = l_loc*32 + r
//  sCk    [26048  .. 29120)  conv weights, step layout [q][a*8+b]
//  sState [29120  .. 34240)  2 x 2560, state[a*320 + l*10 + c]
//  sOut   [34240  .. 34256)  output accumulator (10 used)
#define OFF_X   0
#define OFF_M   9408
#define OFF_G   21952
#define OFF_CK  26048
#define OFF_ST  29120
#define OFF_OUT 34240
#define SMEM_FLOATS 34256

__global__ void __launch_bounds__(THREADS, 1)
tctl_kernel(const float* __restrict__ x,
            const float* __restrict__ cf,   // [Q][CB]
            const float* __restrict__ cm,   // [NMID][CB][Q][CB]
            const float* __restrict__ cl,   // [CB][Q]
            const float* __restrict__ tf,   // [C][P][R]
            const float* __restrict__ tm,   // [NMID][R][P][R]
            const float* __restrict__ tl,   // [R][P]
            float* __restrict__ out)        // [S][C]
{
    extern __shared__ float smem[];
    float* sx     = smem + OFF_X;
    float* sM     = smem + OFF_M;
    float* sG     = smem + OFF_G;
    float* sCk    = smem + OFF_CK;
    float* sState = smem + OFF_ST;
    float* sOut   = smem + OFF_OUT;

    const int tid = threadIdx.x;
    const int s   = blockIdx.x;

    // ---------- load x sample (9408 floats, vectorized) ----------
    {
        const float4* xg = (const float4*)(x + (size_t)s * (P_ * Q_));
        float4* sx4 = (float4*)sx;
        for (int i = tid; i < (P_ * Q_) / 4; i += THREADS) sx4[i] = xg[i];
    }
    // conv_first -> sCk (layout already [q*8+b]); Q*CB = 384 > THREADS, so loop
    for (int i = tid; i < Q_ * CB_; i += THREADS) sCk[i] = cf[i];
    __syncthreads();

    // ---------- carriage 1: y1[p,b] = sum_q x[p,q] cf[q,b]  (into sM[p*8+b]) ----------
    for (int e = tid; e < P_ * CB_; e += THREADS) {
        int p = e >> 3, b = e & 7;
        const float* xp = sx + p * Q_;
        float acc = 0.f;
        #pragma unroll
        for (int q = 0; q < Q_; q++) acc += xp[q] * sCk[q * 8 + b];
        sM[e] = acc;
    }
    __syncthreads();

    // state0[b,r,c] = sum_p y1[p,b] * tf[c,p,r]   (thread t -> b=t>>5, r=t&31)
    {
        const int b = tid >> 5, r = tid & 31;
        float acc[C_];
        #pragma unroll
        for (int c = 0; c < C_; c++) acc[c] = 0.f;
        for (int p = 0; p < P_; p++) {
            float y = sM[p * 8 + b];
            #pragma unroll
            for (int c = 0; c < C_; c++)
                acc[c] += y * tf[((size_t)c * P_ + p) * R_ + r];
        }
        #pragma unroll
        for (int c = 0; c < C_; c++) sState[b * 320 + r * 10 + c] = acc[c];
    }

    // ---------- mid carriages ----------
    const int rowGrp = tid >> 4;        // 0..15 -> G rows ab = rowGrp*4 .. +3
    const int colGrp = tid & 15;        // 0..15 -> G cols colGrp*4 .. +3
    const int bT = tid >> 5;            // state-update mapping: thread = (b, r)
    const int rT = tid & 31;

    for (int k = 0; k < NMID; k++) {
        const float* Ck = cm + (size_t)k * (CB_ * Q_ * CB_);
        const float* Ak = tm + (size_t)k * (R_ * P_ * R_);
        float* stCur = sState + (k & 1) * 2560;
        float* stNxt = sState + ((k & 1) ^ 1) * 2560;

        __syncthreads();  // guard sCk/sM overwrite + state writes from prev step

        // load Ck into sCk as [q][a*8+b]
        for (int i = tid; i < CB_ * Q_ * CB_; i += THREADS) {
            int a  = i / (Q_ * CB_);
            int qb = i % (Q_ * CB_);
            int q = qb >> 3, b = qb & 7;
            sCk[q * 64 + a * 8 + b] = Ck[i];
        }
        __syncthreads();

        // M[p][ab] = sum_q x[p,q] * Ck[a,q,b]  (float4 over ab)
        for (int e4 = tid; e4 < (P_ * 64) / 4; e4 += THREADS) {
            int p  = e4 >> 4;
            int c4 = e4 & 15;
            const float*  xp  = sx + p * Q_;
            const float4* ck4 = ((const float4*)sCk) + c4;
            float4 acc = make_float4(0.f, 0.f, 0.f, 0.f);
            #pragma unroll
            for (int q = 0; q < Q_; q++) {
                float  f  = xp[q];
                float4 cv = ck4[q * 16];
                acc.x += f * cv.x; acc.y += f * cv.y;
                acc.z += f * cv.z; acc.w += f * cv.w;
            }
            ((float4*)sM)[e4] = acc;
        }
        // (barrier before first tile read is inside the tile loop)

        float ns[C_];
        #pragma unroll
        for (int c = 0; c < C_; c++) ns[c] = 0.f;

        // 16 tiles over l-pairs; tile cols = (l_loc in {0,1}) * 32 + r
        for (int lt = 0; lt < 16; lt++) {
            __syncthreads();  // sM ready / previous tile's sG fully consumed

            const int   l   = lt * 2 + (colGrp >> 3);
            const int   r0  = (colGrp & 7) * 4;
            const float* AkL = Ak + (size_t)l * (P_ * R_) + r0;
            const float4* mrow = ((const float4*)sM) + rowGrp;

            float4 a0 = make_float4(0.f,0.f,0.f,0.f);
            float4 a1 = make_float4(0.f,0.f,0.f,0.f);
            float4 a2 = make_float4(0.f,0.f,0.f,0.f);
            float4 a3 = make_float4(0.f,0.f,0.f,0.f);

            #pragma unroll 2
            for (int p = 0; p < P_; p++) {
                float4 av = *(const float4*)(AkL + (size_t)p * R_);
                float4 mv = mrow[p * 16];
                a0.x += mv.x * av.x; a0.y += mv.x * av.y; a0.z += mv.x * av.z; a0.w += mv.x * av.w;
                a1.x += mv.y * av.x; a1.y += mv.y * av.y; a1.z += mv.y * av.z; a1.w += mv.y * av.w;
                a2.x += mv.z * av.x; a2.y += mv.z * av.y; a2.z += mv.z * av.z; a2.w += mv.z * av.w;
                a3.x += mv.w * av.x; a3.y += mv.w * av.y; a3.z += mv.w * av.z; a3.w += mv.w * av.w;
            }

            float4* g4 = (float4*)sG;
            g4[(rowGrp * 4 + 0) * 16 + colGrp] = a0;
            g4[(rowGrp * 4 + 1) * 16 + colGrp] = a1;
            g4[(rowGrp * 4 + 2) * 16 + colGrp] = a2;
            g4[(rowGrp * 4 + 3) * 16 + colGrp] = a3;
            __syncthreads();

            // ns[c] += sum_{a, lj} state[a, lt*2+lj, c] * G[a*8+bT, lj*32+rT]
            #pragma unroll
            for (int a = 0; a < CB_; a++) {
                #pragma unroll
                for (int lj = 0; lj < 2; lj++) {
                    float g = sG[(a * 8 + bT) * 64 + lj * 32 + rT];
                    const float* st = stCur + a * 320 + (lt * 2 + lj) * 10;
                    #pragma unroll
                    for (int c = 0; c < C_; c++) ns[c] += st[c] * g;
                }
            }
        }

        #pragma unroll
        for (int c = 0; c < C_; c++) stNxt[bT * 320 + rT * 10 + c] = ns[c];
    }

    // ---------- last carriage ----------
    __syncthreads();  // all tile reads of sM / state writes done

    // z[p,a] = sum_q x[p,q] cl[a,q]  (into sM[p*8+a])
    for (int e = tid; e < P_ * CB_; e += THREADS) {
        int p = e >> 3, a = e & 7;
        const float* xp  = sx + p * Q_;
        const float* cla = cl + a * Q_;
        float acc = 0.f;
        #pragma unroll
        for (int q = 0; q < Q_; q++) acc += xp[q] * cla[q];
        sM[e] = acc;
    }
    if (tid < C_) sOut[tid] = 0.f;
    __syncthreads();

    // GN[a,l] = sum_p z[p,a] tl[l,p];  out[c] = sum_{a,l} state[a,l,c] * GN[a,l]
    {
        const int a = tid >> 5, l = tid & 31;
        const float* tlr = tl + l * P_;
        float gn = 0.f;
        for (int p = 0; p < P_; p++) gn += sM[p * 8 + a] * tlr[p];

        const float* st = sState + /*final buffer 0 (NMID even)*/ a * 320 + l * 10;
        #pragma unroll
        for (int c = 0; c < C_; c++) atomicAdd(&sOut[c], st[c] * gn);
    }
    __syncthreads();

    if (tid < C_) out[(size_t)s * C_ + tid] = sOut[tid];
}

extern "C" void kernel_launch(void* const* d_in, const int* in_sizes, int n_in,
                              void* d_out, int out_size)
{
    const float* x  = (const float*)d_in[0];
    const float* cf = (const float*)d_in[1];
    const float* cm = (const float*)d_in[2];
    const float* cl = (const float*)d_in[3];
    const float* tf = (const float*)d_in[4];
    const float* tm = (const float*)d_in[5];
    const float* tl = (const float*)d_in[6];
    float* out = (float*)d_out;

    size_t shbytes = SMEM_FLOATS * sizeof(float);
    cudaFuncSetAttribute(tctl_kernel, cudaFuncAttributeMaxDynamicSharedMemorySize,
                         (int)shbytes);
    tctl_kernel<<<S_, THREADS, shbytes>>>(x, cf, cm, cl, tf, tm, tl, out);
}

// round 3
// speedup vs baseline: 2.6146x; 2.6146x over previous
#include <cuda_runtime.h>

#define S_    512
#define P_    196
#define Q_    48
#define CB_   8
#define R_    32
#define C_    10
#define NMID  6

#define THREADS 512

// shared memory layout (floats)
#define OFF_X   0                      // 9408   x[p][q]
#define OFF_M   9408                   // 12544  M[p][ab]
#define OFF_G   21952                  // 2*8192 G tile double buffer [ab(64)][col(128)]
#define OFF_CK  38336                  // 3072   Ck as [q][a*8+b]
#define OFF_ST  41408                  // 2*2560 state[a*320 + l*10 + c]
#define OFF_OUT 46528                  // 16
#define SMEM_FLOATS 46544

__global__ void __launch_bounds__(THREADS, 1)
tctl_kernel(const float* __restrict__ x,
            const float* __restrict__ cf,   // [Q][CB]
            const float* __restrict__ cm,   // [NMID][CB][Q][CB]
            const float* __restrict__ cl,   // [CB][Q]
            const float* __restrict__ tf,   // [C][P][R]
            const float* __restrict__ tm,   // [NMID][R][P][R]
            const float* __restrict__ tl,   // [R][P]
            float* __restrict__ out)        // [S][C]
{
    extern __shared__ float smem[];
    float* sx     = smem + OFF_X;
    float* sM     = smem + OFF_M;
    float* sG     = smem + OFF_G;
    float* sCk    = smem + OFF_CK;
    float* sState = smem + OFF_ST;
    float* sOut   = smem + OFF_OUT;

    const int tid = threadIdx.x;
    const int s   = blockIdx.x;

    // ---------- load x sample ----------
    {
        const float4* xg = (const float4*)(x + (size_t)s * (P_ * Q_));
        float4* sx4 = (float4*)sx;
        for (int i = tid; i < (P_ * Q_) / 4; i += THREADS) sx4[i] = xg[i];
    }
    for (int i = tid; i < Q_ * CB_; i += THREADS) sCk[i] = cf[i];
    __syncthreads();

    // ---------- carriage 1: y1[p,b] = sum_q x[p,q] cf[q,b]  (into sM[p*8+b]) ----------
    for (int e = tid; e < P_ * CB_; e += THREADS) {
        int p = e >> 3, b = e & 7;
        const float* xp = sx + p * Q_;
        float acc = 0.f;
        #pragma unroll
        for (int q = 0; q < Q_; q++) acc += xp[q] * sCk[q * 8 + b];
        sM[e] = acc;
    }
    __syncthreads();

    // state0[b,r,c] = sum_p y1[p,b] * tf[c,p,r]   (threads 0..255: b=t>>5, r=t&31)
    if (tid < 256) {
        const int b = tid >> 5, r = tid & 31;
        float acc[C_];
        #pragma unroll
        for (int c = 0; c < C_; c++) acc[c] = 0.f;
        for (int p = 0; p < P_; p++) {
            float y = sM[p * 8 + b];
            #pragma unroll
            for (int c = 0; c < C_; c++)
                acc[c] += y * tf[((size_t)c * P_ + p) * R_ + r];
        }
        #pragma unroll
        for (int c = 0; c < C_; c++) sState[b * 320 + r * 10 + c] = acc[c];
    }

    // ---------- mid carriages ----------
    const int rowGrp = tid >> 5;        // 0..15 -> G rows ab = rowGrp*4..+3
    const int colGrp = tid & 31;        // 0..31 -> G cols colGrp*4..+3 (of 128)
    // state-update mapping: b = tid>>6 (0..7), rr = (tid>>1)&31, ch = tid&1 (c half)
    const int bU  = tid >> 6;
    const int rU  = (tid >> 1) & 31;
    const int chU = tid & 1;

    for (int k = 0; k < NMID; k++) {
        const float* Ck = cm + (size_t)k * (CB_ * Q_ * CB_);
        const float* Ak = tm + (size_t)k * (R_ * P_ * R_);
        float* stCur = sState + (k & 1) * 2560;
        float* stNxt = sState + ((k & 1) ^ 1) * 2560;

        __syncthreads();  // state writes + last step's sM reads done

        // Ck -> sCk as [q][a*8+b]
        for (int i = tid; i < CB_ * Q_ * CB_; i += THREADS) {
            int a  = i / (Q_ * CB_);
            int qb = i % (Q_ * CB_);
            int q = qb >> 3, b = qb & 7;
            sCk[q * 64 + a * 8 + b] = Ck[i];
        }
        __syncthreads();

        // M[p][ab] = sum_q x[p,q] * Ck[a,q,b]
        for (int e4 = tid; e4 < (P_ * 64) / 4; e4 += THREADS) {
            int p  = e4 >> 4;
            int c4 = e4 & 15;
            const float*  xp  = sx + p * Q_;
            const float4* ck4 = ((const float4*)sCk) + c4;
            float4 acc = make_float4(0.f, 0.f, 0.f, 0.f);
            #pragma unroll
            for (int q = 0; q < Q_; q++) {
                float  f  = xp[q];
                float4 cv = ck4[q * 16];
                acc.x += f * cv.x; acc.y += f * cv.y;
                acc.z += f * cv.z; acc.w += f * cv.w;
            }
            ((float4*)sM)[e4] = acc;
        }
        __syncthreads();  // sM ready for tile reads

        float ns[5];
        #pragma unroll
        for (int c = 0; c < 5; c++) ns[c] = 0.f;

        // 8 tiles over groups of 4 l-values; G tile [64 rows][4*32 cols], double-buffered
        for (int lt = 0; lt < 8; lt++) {
            float* gbuf = sG + (lt & 1) * 8192;

            const int   l   = lt * 4 + (colGrp >> 3);
            const int   r0  = (colGrp & 7) * 4;
            const float* AkL = Ak + (size_t)l * (P_ * R_) + r0;
            const float4* mrow = ((const float4*)sM) + rowGrp;

            float4 a0 = make_float4(0.f,0.f,0.f,0.f);
            float4 a1 = make_float4(0.f,0.f,0.f,0.f);
            float4 a2 = make_float4(0.f,0.f,0.f,0.f);
            float4 a3 = make_float4(0.f,0.f,0.f,0.f);

            // software-pipelined p loop
            float4 av = *(const float4*)(AkL);
            float4 mv = mrow[0];
            #pragma unroll 4
            for (int p = 0; p < P_ - 1; p++) {
                float4 av2 = *(const float4*)(AkL + (size_t)(p + 1) * R_);
                float4 mv2 = mrow[(p + 1) * 16];
                a0.x += mv.x * av.x; a0.y += mv.x * av.y; a0.z += mv.x * av.z; a0.w += mv.x * av.w;
                a1.x += mv.y * av.x; a1.y += mv.y * av.y; a1.z += mv.y * av.z; a1.w += mv.y * av.w;
                a2.x += mv.z * av.x; a2.y += mv.z * av.y; a2.z += mv.z * av.z; a2.w += mv.z * av.w;
                a3.x += mv.w * av.x; a3.y += mv.w * av.y; a3.z += mv.w * av.z; a3.w += mv.w * av.w;
                av = av2; mv = mv2;
            }
            a0.x += mv.x * av.x; a0.y += mv.x * av.y; a0.z += mv.x * av.z; a0.w += mv.x * av.w;
            a1.x += mv.y * av.x; a1.y += mv.y * av.y; a1.z += mv.y * av.z; a1.w += mv.y * av.w;
            a2.x += mv.z * av.x; a2.y += mv.z * av.y; a2.z += mv.z * av.z; a2.w += mv.z * av.w;
            a3.x += mv.w * av.x; a3.y += mv.w * av.y; a3.z += mv.w * av.z; a3.w += mv.w * av.w;

            float4* g4 = (float4*)gbuf;
            g4[(rowGrp * 4 + 0) * 32 + colGrp] = a0;
            g4[(rowGrp * 4 + 1) * 32 + colGrp] = a1;
            g4[(rowGrp * 4 + 2) * 32 + colGrp] = a2;
            g4[(rowGrp * 4 + 3) * 32 + colGrp] = a3;
            __syncthreads();  // gbuf complete (and prev tile's update finished)

            // ns[c] += sum_{a,lj} state[a, lt*4+lj, c] * G[a*8+bU, lj*32+rU]
            #pragma unroll
            for (int a = 0; a < CB_; a++) {
                #pragma unroll
                for (int lj = 0; lj < 4; lj++) {
                    float g = gbuf[(a * 8 + bU) * 128 + lj * 32 + rU];
                    const float* st = stCur + a * 320 + (lt * 4 + lj) * 10 + chU * 5;
                    #pragma unroll
                    for (int c = 0; c < 5; c++) ns[c] += st[c] * g;
                }
            }
        }

        #pragma unroll
        for (int c = 0; c < 5; c++) stNxt[bU * 320 + rU * 10 + chU * 5 + c] = ns[c];
    }

    // ---------- last carriage ----------
    __syncthreads();

    // z[p,a] = sum_q x[p,q] cl[a,q]  (into sM[p*8+a])
    for (int e = tid; e < P_ * CB_; e += THREADS) {
        int p = e >> 3, a = e & 7;
        const float* xp  = sx + p * Q_;
        const float* cla = cl + a * Q_;
        float acc = 0.f;
        #pragma unroll
        for (int q = 0; q < Q_; q++) acc += xp[q] * cla[q];
        sM[e] = acc;
    }
    if (tid < C_) sOut[tid] = 0.f;
    __syncthreads();

    // GN[a,l] = sum_p z[p,a] tl[l,p];  out[c] = sum_{a,l} state[a,l,c]*GN[a,l]
    if (tid < 256) {
        const int a = tid >> 5, l = tid & 31;
        const float* tlr = tl + l * P_;
        float gn = 0.f;
        for (int p = 0; p < P_; p++) gn += sM[p * 8 + a] * tlr[p];

        const float* st = sState + /*final buffer 0 (NMID even)*/ a * 320 + l * 10;
        #pragma unroll
        for (int c = 0; c < C_; c++) atomicAdd(&sOut[c], st[c] * gn);
    }
    __syncthreads();

    if (tid < C_) out[(size_t)s * C_ + tid] = sOut[tid];
}

extern "C" void kernel_launch(void* const* d_in, const int* in_sizes, int n_in,
                              void* d_out, int out_size)
{
    const float* x  = (const float*)d_in[0];
    const float* cf = (const float*)d_in[1];
    const float* cm = (const float*)d_in[2];
    const float* cl = (const float*)d_in[3];
    const float* tf = (const float*)d_in[4];
    const float* tm = (const float*)d_in[5];
    const float* tl = (const float*)d_in[6];
    float* out = (float*)d_out;

    size_t shbytes = SMEM_FLOATS * sizeof(float);
    cudaFuncSetAttribute(tctl_kernel, cudaFuncAttributeMaxDynamicSharedMemorySize,
                         (int)shbytes);
    tctl_kernel<<<S_, THREADS, shbytes>>>(x, cf, cm, cl, tf, tm, tl, out);
}